// round 12
// baseline (speedup 1.0000x reference)
#include <cuda_runtime.h>
#include <cstdint>
#include <cstddef>

#define DI __device__ __forceinline__

constexpr int Bn = 8, Nn = 1024, Dn = 256, Hn = 4;
constexpr int ROWS = Bn * Nn;  // 8192

// -------- scratch (static device globals: allocation-free) --------
__device__ float g_Q[ROWS * Dn];
__device__ float g_K[ROWS * Dn];
__device__ float g_V[ROWS * Dn];
__device__ float g_M[ROWS * Dn];
__device__ float g_S[(size_t)Bn * Hn * Nn * Nn];  // 134 MB score scratch

// -------- packed f32x2 helpers --------
DI unsigned long long pack2(float lo, float hi) {
    unsigned long long r;
    asm("mov.b64 %0, {%1, %2};" : "=l"(r) : "f"(lo), "f"(hi));
    return r;
}
DI void fma2(unsigned long long& d, unsigned long long a, unsigned long long b) {
    asm("fma.rn.f32x2 %0, %1, %2, %0;" : "+l"(d) : "l"(a), "l"(b));
}
DI float2 unpack2(unsigned long long v) {
    float lo, hi;
    asm("mov.b64 {%0, %1}, %2;" : "=f"(lo), "=f"(hi) : "l"(v));
    return make_float2(lo, hi);
}

// monotone float->uint mapping (order-preserving)
DI unsigned mapf(float x) {
    unsigned b = __float_as_uint(x);
    return (b & 0x80000000u) ? ~b : (b | 0x80000000u);
}
DI float invmap(unsigned u) {
    unsigned b = (u & 0x80000000u) ? (u & 0x7FFFFFFFu) : ~u;
    return __uint_as_float(b);
}

// inner 8x8 f32x2 FMA block
#define MMA_KK(AS, BS)                                                        \
    {                                                                         \
        float4 a0 = *(const float4*)&AS[trow];                                \
        float4 a1 = *(const float4*)&AS[trow + 4];                            \
        ulonglong2 b0 = *(const ulonglong2*)&BS[c0];                          \
        ulonglong2 b1 = *(const ulonglong2*)&BS[c0 + 64];                     \
        unsigned long long ad[8];                                             \
        ad[0] = pack2(a0.x, a0.x); ad[1] = pack2(a0.y, a0.y);                 \
        ad[2] = pack2(a0.z, a0.z); ad[3] = pack2(a0.w, a0.w);                 \
        ad[4] = pack2(a1.x, a1.x); ad[5] = pack2(a1.y, a1.y);                 \
        ad[6] = pack2(a1.z, a1.z); ad[7] = pack2(a1.w, a1.w);                 \
        _Pragma("unroll")                                                     \
        for (int i_ = 0; i_ < 8; ++i_) {                                      \
            fma2(acc[i_][0], ad[i_], b0.x);                                   \
            fma2(acc[i_][1], ad[i_], b0.y);                                   \
            fma2(acc[i_][2], ad[i_], b1.x);                                   \
            fma2(acc[i_][3], ad[i_], b1.y);                                   \
        }                                                                     \
    }

// ============================================================================
// Fused QKV GEMM: 64x128 tile, 128 thr, 8x8/thread, BK=8 double-buffered.
// Reg cap raised to ~168 (3 CTAs/SM) for ptxas load pipelining.
// ============================================================================
__global__ void __launch_bounds__(128, 3) gemm_qkv_kernel(
    const float* __restrict__ A,
    const float* __restrict__ W0, const float* __restrict__ W1, const float* __restrict__ W2,
    const float* __restrict__ b0_, const float* __restrict__ b1_, const float* __restrict__ b2_,
    float* __restrict__ C0, float* __restrict__ C1, float* __restrict__ C2)
{
    __shared__ __align__(16) float As[2][8][68];
    __shared__ __align__(16) float Bs[2][8][132];

    const int z = blockIdx.z;
    const float* W    = (z == 0) ? W0  : (z == 1) ? W1  : W2;
    const float* bias = (z == 0) ? b0_ : (z == 1) ? b1_ : b2_;
    float*       C    = (z == 0) ? C0  : (z == 1) ? C1  : C2;

    const int tid  = threadIdx.x;
    const int m0   = blockIdx.y * 64;
    const int n0   = blockIdx.x * 128;
    const int trow = (tid >> 4) << 3;
    const int c0   = (tid & 15) << 2;
    const int r    = tid >> 1;
    const int q    = (tid & 1) << 2;

    const float* Ap  = A + (size_t)(m0 + r) * 256 + q;
    const float* Wp0 = W + (size_t)(n0 + r) * 256 + q;
    const float* Wp1 = W + (size_t)(n0 + r + 64) * 256 + q;

    unsigned long long acc[8][4];
#pragma unroll
    for (int i = 0; i < 8; ++i)
#pragma unroll
        for (int p = 0; p < 4; ++p) acc[i][p] = 0ULL;

    {
        float4 av  = *(const float4*)Ap;
        float4 wv0 = *(const float4*)Wp0;
        float4 wv1 = *(const float4*)Wp1;
        As[0][q + 0][r] = av.x;  As[0][q + 1][r] = av.y;
        As[0][q + 2][r] = av.z;  As[0][q + 3][r] = av.w;
        Bs[0][q + 0][r] = wv0.x; Bs[0][q + 1][r] = wv0.y;
        Bs[0][q + 2][r] = wv0.z; Bs[0][q + 3][r] = wv0.w;
        Bs[0][q + 0][r + 64] = wv1.x; Bs[0][q + 1][r + 64] = wv1.y;
        Bs[0][q + 2][r + 64] = wv1.z; Bs[0][q + 3][r + 64] = wv1.w;
    }
    __syncthreads();

#pragma unroll 2
    for (int it = 0; it < 32; ++it) {
        const int cur = it & 1;
        float4 avn, wvn0, wvn1;
        if (it < 31) {
            avn  = *(const float4*)(Ap  + (it + 1) * 8);
            wvn0 = *(const float4*)(Wp0 + (it + 1) * 8);
            wvn1 = *(const float4*)(Wp1 + (it + 1) * 8);
        }
#pragma unroll
        for (int kk = 0; kk < 8; ++kk) {
            MMA_KK(As[cur][kk], Bs[cur][kk]);
        }
        if (it < 31) {
            const int nxt = cur ^ 1;
            As[nxt][q + 0][r] = avn.x;  As[nxt][q + 1][r] = avn.y;
            As[nxt][q + 2][r] = avn.z;  As[nxt][q + 3][r] = avn.w;
            Bs[nxt][q + 0][r] = wvn0.x; Bs[nxt][q + 1][r] = wvn0.y;
            Bs[nxt][q + 2][r] = wvn0.z; Bs[nxt][q + 3][r] = wvn0.w;
            Bs[nxt][q + 0][r + 64] = wvn1.x; Bs[nxt][q + 1][r + 64] = wvn1.y;
            Bs[nxt][q + 2][r + 64] = wvn1.z; Bs[nxt][q + 3][r + 64] = wvn1.w;
            __syncthreads();
        }
    }

    float4 bb0 = *(const float4*)&bias[n0 + c0];
    float4 bb1 = *(const float4*)&bias[n0 + c0 + 64];
#pragma unroll
    for (int i = 0; i < 8; ++i) {
        int m = m0 + trow + i;
        float2 v0 = unpack2(acc[i][0]), v1 = unpack2(acc[i][1]);
        float2 v2 = unpack2(acc[i][2]), v3 = unpack2(acc[i][3]);
        float4 o0 = make_float4(v0.x + bb0.x, v0.y + bb0.y, v1.x + bb0.z, v1.y + bb0.w);
        float4 o1 = make_float4(v2.x + bb1.x, v2.y + bb1.y, v3.x + bb1.z, v3.y + bb1.w);
        *(float4*)&C[(size_t)m * 256 + n0 + c0]      = o0;
        *(float4*)&C[(size_t)m * 256 + n0 + c0 + 64] = o1;
    }
}

// ============================================================================
// Out-projection GEMM: 32x128 tile, 128 thr, 4x8/thread, BK=16 single-buffer.
// Low regs (~64) -> many resident CTAs; grid 512 -> latency well hidden.
// ============================================================================
__global__ void __launch_bounds__(128, 8) gemm_out_kernel(
    const float* __restrict__ A, const float* __restrict__ W,
    const float* __restrict__ bias, float* __restrict__ C)
{
    __shared__ __align__(16) float As[16][36];
    __shared__ __align__(16) float Bs[16][132];

    const int tid  = threadIdx.x;
    const int m0   = blockIdx.y * 32;
    const int n0   = blockIdx.x * 128;
    const int trow = (tid >> 4) << 2;   // 0..28
    const int c0   = (tid & 15) << 2;   // 0..60
    const int ra   = tid >> 2;          // 0..31
    const int qa   = (tid & 3) << 2;    // 0,4,8,12

    unsigned long long acc[4][4];
#pragma unroll
    for (int i = 0; i < 4; ++i)
#pragma unroll
        for (int p = 0; p < 4; ++p) acc[i][p] = 0ULL;

    const float* Ap = A + (size_t)(m0 + ra) * 256 + qa;
    const float* Wp = W + (size_t)(n0 + tid) * 256;

    for (int kb = 0; kb < 256; kb += 16) {
        float4 av = *(const float4*)(Ap + kb);
        float4 w0 = *(const float4*)(Wp + kb);
        float4 w1 = *(const float4*)(Wp + kb + 4);
        float4 w2 = *(const float4*)(Wp + kb + 8);
        float4 w3 = *(const float4*)(Wp + kb + 12);
        __syncthreads();
        As[qa + 0][ra] = av.x; As[qa + 1][ra] = av.y;
        As[qa + 2][ra] = av.z; As[qa + 3][ra] = av.w;
        Bs[0][tid]  = w0.x; Bs[1][tid]  = w0.y; Bs[2][tid]  = w0.z; Bs[3][tid]  = w0.w;
        Bs[4][tid]  = w1.x; Bs[5][tid]  = w1.y; Bs[6][tid]  = w1.z; Bs[7][tid]  = w1.w;
        Bs[8][tid]  = w2.x; Bs[9][tid]  = w2.y; Bs[10][tid] = w2.z; Bs[11][tid] = w2.w;
        Bs[12][tid] = w3.x; Bs[13][tid] = w3.y; Bs[14][tid] = w3.z; Bs[15][tid] = w3.w;
        __syncthreads();
#pragma unroll
        for (int kk = 0; kk < 16; ++kk) {
            float4 a = *(const float4*)&As[kk][trow];
            ulonglong2 b0 = *(const ulonglong2*)&Bs[kk][c0];
            ulonglong2 b1 = *(const ulonglong2*)&Bs[kk][c0 + 64];
            unsigned long long ad[4];
            ad[0] = pack2(a.x, a.x); ad[1] = pack2(a.y, a.y);
            ad[2] = pack2(a.z, a.z); ad[3] = pack2(a.w, a.w);
#pragma unroll
            for (int i = 0; i < 4; ++i) {
                fma2(acc[i][0], ad[i], b0.x);
                fma2(acc[i][1], ad[i], b0.y);
                fma2(acc[i][2], ad[i], b1.x);
                fma2(acc[i][3], ad[i], b1.y);
            }
        }
    }

    float4 bb0 = *(const float4*)&bias[n0 + c0];
    float4 bb1 = *(const float4*)&bias[n0 + c0 + 64];
#pragma unroll
    for (int i = 0; i < 4; ++i) {
        int m = m0 + trow + i;
        float2 v0 = unpack2(acc[i][0]), v1 = unpack2(acc[i][1]);
        float2 v2 = unpack2(acc[i][2]), v3 = unpack2(acc[i][3]);
        float4 o0 = make_float4(v0.x + bb0.x, v0.y + bb0.y, v1.x + bb0.z, v1.y + bb0.w);
        float4 o1 = make_float4(v2.x + bb1.x, v2.y + bb1.y, v3.x + bb1.z, v3.y + bb1.w);
        *(float4*)&C[(size_t)m * 256 + n0 + c0]      = o0;
        *(float4*)&C[(size_t)m * 256 + n0 + c0 + 64] = o1;
    }
}

// ============================================================================
// Scores: 64x128 tile, 128 thr, 8x8/thread, BK=8 double-buffered, reg cap 168.
// ============================================================================
__global__ void __launch_bounds__(128, 3) scores_kernel(const float* __restrict__ td)
{
    __shared__ __align__(16) float As[2][8][68];
    __shared__ __align__(16) float Bs[2][8][132];

    const int tid  = threadIdx.x;
    const int bh   = blockIdx.z;
    const int b    = bh >> 2;
    const int h    = bh & 3;
    const int i0   = blockIdx.y * 64;
    const int j0   = blockIdx.x * 128;
    const int trow = (tid >> 4) << 3;
    const int c0   = (tid & 15) << 2;
    const int r    = tid >> 1;
    const int q    = (tid & 1) << 2;

    const float* Qp  = g_Q + ((size_t)(b * Nn) + i0 + r) * 256 + h * 64 + q;
    const float* Kp0 = g_K + ((size_t)(b * Nn) + j0 + r) * 256 + h * 64 + q;
    const float* Kp1 = g_K + ((size_t)(b * Nn) + j0 + r + 64) * 256 + h * 64 + q;

    unsigned long long acc[8][4];
#pragma unroll
    for (int i = 0; i < 8; ++i)
#pragma unroll
        for (int p = 0; p < 4; ++p) acc[i][p] = 0ULL;

    {
        float4 av  = *(const float4*)Qp;
        float4 bv0 = *(const float4*)Kp0;
        float4 bv1 = *(const float4*)Kp1;
        As[0][q + 0][r] = av.x;  As[0][q + 1][r] = av.y;
        As[0][q + 2][r] = av.z;  As[0][q + 3][r] = av.w;
        Bs[0][q + 0][r] = bv0.x; Bs[0][q + 1][r] = bv0.y;
        Bs[0][q + 2][r] = bv0.z; Bs[0][q + 3][r] = bv0.w;
        Bs[0][q + 0][r + 64] = bv1.x; Bs[0][q + 1][r + 64] = bv1.y;
        Bs[0][q + 2][r + 64] = bv1.z; Bs[0][q + 3][r + 64] = bv1.w;
    }
    __syncthreads();

#pragma unroll 2
    for (int it = 0; it < 8; ++it) {
        const int cur = it & 1;
        float4 avn, bvn0, bvn1;
        if (it < 7) {
            avn  = *(const float4*)(Qp  + (it + 1) * 8);
            bvn0 = *(const float4*)(Kp0 + (it + 1) * 8);
            bvn1 = *(const float4*)(Kp1 + (it + 1) * 8);
        }
#pragma unroll
        for (int kk = 0; kk < 8; ++kk) {
            MMA_KK(As[cur][kk], Bs[cur][kk]);
        }
        if (it < 7) {
            const int nxt = cur ^ 1;
            As[nxt][q + 0][r] = avn.x;  As[nxt][q + 1][r] = avn.y;
            As[nxt][q + 2][r] = avn.z;  As[nxt][q + 3][r] = avn.w;
            Bs[nxt][q + 0][r] = bvn0.x; Bs[nxt][q + 1][r] = bvn0.y;
            Bs[nxt][q + 2][r] = bvn0.z; Bs[nxt][q + 3][r] = bvn0.w;
            Bs[nxt][q + 0][r + 64] = bvn1.x; Bs[nxt][q + 1][r + 64] = bvn1.y;
            Bs[nxt][q + 2][r + 64] = bvn1.z; Bs[nxt][q + 3][r + 64] = bvn1.w;
            __syncthreads();
        }
    }

#pragma unroll
    for (int i = 0; i < 8; ++i) {
        int gi = i0 + trow + i;
        const float4* tdr = (const float4*)(td + ((size_t)b * Nn + gi) * Nn + j0);
        float4* Sr = (float4*)(g_S + ((size_t)bh * Nn + gi) * Nn + j0);
        float4 t0 = __ldcs(&tdr[c0 >> 2]);
        float4 t1 = __ldcs(&tdr[(c0 + 64) >> 2]);
        float2 v0 = unpack2(acc[i][0]), v1 = unpack2(acc[i][1]);
        float2 v2 = unpack2(acc[i][2]), v3 = unpack2(acc[i][3]);
        float4 o0 = make_float4(v0.x * 0.125f - 0.1f * t0.x,
                                v0.y * 0.125f - 0.1f * t0.y,
                                v1.x * 0.125f - 0.1f * t0.z,
                                v1.y * 0.125f - 0.1f * t0.w);
        float4 o1 = make_float4(v2.x * 0.125f - 0.1f * t1.x,
                                v2.y * 0.125f - 0.1f * t1.y,
                                v3.x * 0.125f - 0.1f * t1.z,
                                v3.y * 0.125f - 0.1f * t1.w);
        __stcs(&Sr[c0 >> 2], o0);
        __stcs(&Sr[(c0 + 64) >> 2], o1);
    }
}

// ============================================================================
// Fused, 2 rows per CTA, 4 CTAs/SM. 8-wide V gather.
// ============================================================================
constexpr int SURV_CAP = 128;
constexpr int LIST_CAP = 144;

__global__ void __launch_bounds__(256, 4) fused_attn_kernel(
    const int* __restrict__ topk_ptr, float* __restrict__ out_adj)
{
    __shared__ __align__(16) float sc[2][4][1024];
    __shared__ __align__(16) float adjs[2][1024];
    __shared__ unsigned s_surv[8][SURV_CAP];
    __shared__ int   jl[8][LIST_CAP];
    __shared__ float av[8][LIST_CAP];
    __shared__ float s_kth[8];
    __shared__ float s_max[8];

    const int tid  = threadIdx.x;
    const int row0 = blockIdx.x * 2;
    const int b    = row0 >> 10;
    const int i0   = row0 & 1023;
    const int warp = tid >> 5, lane = tid & 31;
    const int wp   = warp >> 2;
    const int wh   = warp & 3;

#pragma unroll
    for (int p = 0; p < 2; ++p)
#pragma unroll
        for (int h = 0; h < 4; ++h) {
            const float4* src = (const float4*)(g_S +
                (((size_t)(b * 4 + h) * Nn + (i0 + p)) * Nn));
            ((float4*)sc[p][h])[tid] = __ldcs(&src[tid]);
        }
#pragma unroll
    for (int p = 0; p < 2; ++p)
        ((float4*)adjs[p])[tid] = make_float4(0.f, 0.f, 0.f, 0.f);
    __syncthreads();

    int kv = *topk_ptr;
    if (kv > Nn) kv = Nn;
    if (kv < 1)  kv = 1;

    // ---- selection: every warp owns one (row, head) ----
    {
        const float* row = sc[wp][wh];

        unsigned lmax = 0u;
#pragma unroll
        for (int e = 0; e < 32; ++e)
            lmax = umax(lmax, mapf(row[e * 32 + lane]));
        const unsigned T0 = __reduce_min_sync(0xffffffffu, lmax);
        const unsigned Mx = __reduce_max_sync(0xffffffffu, lmax);

        unsigned* su = s_surv[warp];
        int base = 0;
#pragma unroll
        for (int e = 0; e < 32; ++e) {
            unsigned u = mapf(row[e * 32 + lane]);
            bool p = (u >= T0);
            unsigned m = __ballot_sync(0xffffffffu, p);
            if (p) {
                int pos = base + __popc(m & ((1u << lane) - 1u));
                if (pos < SURV_CAP) su[pos] = u;
            }
            base += __popc(m);
        }
        const int cnt = base;
        __syncwarp();

        unsigned kthU = 0;
        if (kv <= 32 && cnt <= 128) {
            unsigned v0 = (lane      < cnt) ? su[lane]      : 0u;
            unsigned v1 = (lane + 32 < cnt) ? su[lane + 32] : 0u;
            unsigned v2 = (lane + 64 < cnt) ? su[lane + 64] : 0u;
            unsigned v3 = (lane + 96 < cnt) ? su[lane + 96] : 0u;
            unsigned pref = 0; bool got = false;
            for (int bit = 31; bit >= 0; --bit) {
                unsigned cand = pref | (1u << bit);
                unsigned c = (v0 >= cand) + (v1 >= cand) + (v2 >= cand) + (v3 >= cand);
                c = __reduce_add_sync(0xffffffffu, c);
                if (c == (unsigned)kv) {
                    unsigned mn = 0xFFFFFFFFu;
                    if (v0 >= cand) mn = umin(mn, v0);
                    if (v1 >= cand) mn = umin(mn, v1);
                    if (v2 >= cand) mn = umin(mn, v2);
                    if (v3 >= cand) mn = umin(mn, v3);
                    kthU = __reduce_min_sync(0xffffffffu, mn);
                    got = true; break;
                }
                if (c > (unsigned)kv) pref = cand;
            }
            if (!got) kthU = pref;
        } else {
            unsigned pref = 0; bool got = false;
            for (int bit = 31; bit >= 0; --bit) {
                unsigned cand = pref | (1u << bit);
                unsigned c = 0;
#pragma unroll
                for (int e = 0; e < 32; ++e)
                    c += (mapf(row[e * 32 + lane]) >= cand) ? 1u : 0u;
                c = __reduce_add_sync(0xffffffffu, c);
                if (c == (unsigned)kv) {
                    unsigned mn = 0xFFFFFFFFu;
#pragma unroll
                    for (int e = 0; e < 32; ++e) {
                        unsigned u = mapf(row[e * 32 + lane]);
                        if (u >= cand) mn = umin(mn, u);
                    }
                    kthU = __reduce_min_sync(0xffffffffu, mn);
                    got = true; break;
                }
                if (c > (unsigned)kv) pref = cand;
            }
            if (!got) kthU = pref;
        }
        if (lane == 0) { s_kth[warp] = invmap(kthU); s_max[warp] = invmap(Mx); }
    }
    __syncwarp();

    // ---- group phase: warp handles pair (wp, wh) ----
    const float kth = s_kth[warp];
    const float mx  = s_max[warp];
    int*   jlh = jl[warp];
    float* avh = av[warp];
    const float* rowsc = sc[wp][wh];

    int base2 = 0;
#pragma unroll
    for (int r = 0; r < 32; ++r) {
        int j = r * 32 + lane;
        float s = rowsc[j];
        bool p = (s >= kth);
        unsigned m = __ballot_sync(0xffffffffu, p);
        if (p) {
            int pos = base2 + __popc(m & ((1u << lane) - 1u));
            if (pos < LIST_CAP) { jlh[pos] = j; avh[pos] = s; }
        }
        base2 += __popc(m);
    }
    __syncwarp();
    int cnt2 = (base2 > LIST_CAP) ? LIST_CAP : base2;

    float lsum = 0.f;
    for (int l = lane; l < cnt2; l += 32) {
        float e = __expf(avh[l] - mx);
        avh[l] = e;
        lsum += e;
    }
#pragma unroll
    for (int o = 16; o; o >>= 1) lsum += __shfl_xor_sync(0xffffffffu, lsum, o);
    const float inv = 1.f / lsum;

    for (int l = lane; l < cnt2; l += 32) {
        float a = avh[l] * inv;
        avh[l] = a;
        atomicAdd(&adjs[wp][jlh[l]], 0.25f * a);
    }
    __syncwarp();

    // sparse attn @ V: float2 gather, 8-wide unroll (8 LDG.64 in flight)
    {
        const float2* vb2 = (const float2*)(g_V + (size_t)b * Nn * 256 + wh * 64);
        float ax = 0.f, ay = 0.f;
        int l = 0;
        for (; l + 8 <= cnt2; l += 8) {
            float2 x0 = vb2[(size_t)jlh[l]     * 128 + lane];
            float2 x1 = vb2[(size_t)jlh[l + 1] * 128 + lane];
            float2 x2 = vb2[(size_t)jlh[l + 2] * 128 + lane];
            float2 x3 = vb2[(size_t)jlh[l + 3] * 128 + lane];
            float2 x4 = vb2[(size_t)jlh[l + 4] * 128 + lane];
            float2 x5 = vb2[(size_t)jlh[l + 5] * 128 + lane];
            float2 x6 = vb2[(size_t)jlh[l + 6] * 128 + lane];
            float2 x7 = vb2[(size_t)jlh[l + 7] * 128 + lane];
            float a0 = avh[l],     a1 = avh[l + 1], a2 = avh[l + 2], a3 = avh[l + 3];
            float a4 = avh[l + 4], a5 = avh[l + 5], a6 = avh[l + 6], a7 = avh[l + 7];
            ax = fmaf(a0, x0.x, ax); ay = fmaf(a0, x0.y, ay);
            ax = fmaf(a1, x1.x, ax); ay = fmaf(a1, x1.y, ay);
            ax = fmaf(a2, x2.x, ax); ay = fmaf(a2, x2.y, ay);
            ax = fmaf(a3, x3.x, ax); ay = fmaf(a3, x3.y, ay);
            ax = fmaf(a4, x4.x, ax); ay = fmaf(a4, x4.y, ay);
            ax = fmaf(a5, x5.x, ax); ay = fmaf(a5, x5.y, ay);
            ax = fmaf(a6, x6.x, ax); ay = fmaf(a6, x6.y, ay);
            ax = fmaf(a7, x7.x, ax); ay = fmaf(a7, x7.y, ay);
        }
        for (; l < cnt2; ++l) {
            float2 x = vb2[(size_t)jlh[l] * 128 + lane];
            float a = avh[l];
            ax = fmaf(a, x.x, ax); ay = fmaf(a, x.y, ay);
        }
        float2* mrow2 = (float2*)(g_M + ((size_t)(b * Nn) + i0 + wp) * 256 + wh * 64);
        mrow2[lane] = make_float2(ax, ay);
    }
    __syncthreads();

#pragma unroll
    for (int p = 0; p < 2; ++p) {
        float4* arow = (float4*)(out_adj + ((size_t)(b * Nn) + i0 + p) * Nn);
        __stcs(&arow[tid], ((const float4*)adjs[p])[tid]);
    }
}

// ============================================================================
extern "C" void kernel_launch(void* const* d_in, const int* in_sizes, int n_in,
                              void* d_out, int out_size)
{
    const float* h_in = (const float*)d_in[0];
    const float* td   = (const float*)d_in[1];
    const float* Wq   = (const float*)d_in[2];
    const float* bq   = (const float*)d_in[3];
    const float* Wk   = (const float*)d_in[4];
    const float* bk   = (const float*)d_in[5];
    const float* Wv   = (const float*)d_in[6];
    const float* bv   = (const float*)d_in[7];
    const float* Wo   = (const float*)d_in[8];
    const float* bo   = (const float*)d_in[9];
    const int*   tk   = (const int*)d_in[10];

    float* out_adj = (float*)d_out;
    float* out_msg = out_adj + (size_t)Bn * Nn * Nn;

    float *q, *k, *v, *m;
    cudaGetSymbolAddress((void**)&q, g_Q);
    cudaGetSymbolAddress((void**)&k, g_K);
    cudaGetSymbolAddress((void**)&v, g_V);
    cudaGetSymbolAddress((void**)&m, g_M);

    gemm_qkv_kernel<<<dim3(2, 128, 3), 128>>>(h_in, Wq, Wk, Wv, bq, bk, bv, q, k, v);
    scores_kernel<<<dim3(Nn / 128, Nn / 64, Bn * Hn), 128>>>(td);
    fused_attn_kernel<<<ROWS / 2, 256>>>(tk, out_adj);
    gemm_out_kernel<<<dim3(2, 256), 128>>>(m, Wo, bo, out_msg);
}

// round 13
// speedup vs baseline: 1.0757x; 1.0757x over previous
#include <cuda_runtime.h>
#include <cstdint>
#include <cstddef>

#define DI __device__ __forceinline__

constexpr int Bn = 8, Nn = 1024, Dn = 256, Hn = 4;
constexpr int ROWS = Bn * Nn;  // 8192

// -------- scratch (static device globals: allocation-free) --------
__device__ float g_Q[ROWS * Dn];
__device__ float g_K[ROWS * Dn];
__device__ float g_V[ROWS * Dn];
__device__ float g_M[ROWS * Dn];
__device__ float g_S[(size_t)Bn * Hn * Nn * Nn];  // 134 MB score scratch

// -------- packed f32x2 helpers --------
DI unsigned long long pack2(float lo, float hi) {
    unsigned long long r;
    asm("mov.b64 %0, {%1, %2};" : "=l"(r) : "f"(lo), "f"(hi));
    return r;
}
DI void fma2(unsigned long long& d, unsigned long long a, unsigned long long b) {
    asm("fma.rn.f32x2 %0, %1, %2, %0;" : "+l"(d) : "l"(a), "l"(b));
}
DI float2 unpack2(unsigned long long v) {
    float lo, hi;
    asm("mov.b64 {%0, %1}, %2;" : "=f"(lo), "=f"(hi) : "l"(v));
    return make_float2(lo, hi);
}

// monotone float->uint mapping (order-preserving)
DI unsigned mapf(float x) {
    unsigned b = __float_as_uint(x);
    return (b & 0x80000000u) ? ~b : (b | 0x80000000u);
}
DI float invmap(unsigned u) {
    unsigned b = (u & 0x80000000u) ? (u & 0x7FFFFFFFu) : ~u;
    return __uint_as_float(b);
}

// inner 8x8 f32x2 FMA block
#define MMA_KK(AS, BS)                                                        \
    {                                                                         \
        float4 a0 = *(const float4*)&AS[trow];                                \
        float4 a1 = *(const float4*)&AS[trow + 4];                            \
        ulonglong2 b0 = *(const ulonglong2*)&BS[c0];                          \
        ulonglong2 b1 = *(const ulonglong2*)&BS[c0 + 64];                     \
        unsigned long long ad[8];                                             \
        ad[0] = pack2(a0.x, a0.x); ad[1] = pack2(a0.y, a0.y);                 \
        ad[2] = pack2(a0.z, a0.z); ad[3] = pack2(a0.w, a0.w);                 \
        ad[4] = pack2(a1.x, a1.x); ad[5] = pack2(a1.y, a1.y);                 \
        ad[6] = pack2(a1.z, a1.z); ad[7] = pack2(a1.w, a1.w);                 \
        _Pragma("unroll")                                                     \
        for (int i_ = 0; i_ < 8; ++i_) {                                      \
            fma2(acc[i_][0], ad[i_], b0.x);                                   \
            fma2(acc[i_][1], ad[i_], b0.y);                                   \
            fma2(acc[i_][2], ad[i_], b1.x);                                   \
            fma2(acc[i_][3], ad[i_], b1.y);                                   \
        }                                                                     \
    }

// ============================================================================
// Fused QKV / out-proj GEMM (R11): 64x128 tile, 128 thr, 8x8/thread,
// BK=8 double-buffered. z selects (W,b,C).
// ============================================================================
__global__ void __launch_bounds__(128, 4) gemm_qkv_kernel(
    const float* __restrict__ A,
    const float* __restrict__ W0, const float* __restrict__ W1, const float* __restrict__ W2,
    const float* __restrict__ b0_, const float* __restrict__ b1_, const float* __restrict__ b2_,
    float* __restrict__ C0, float* __restrict__ C1, float* __restrict__ C2)
{
    __shared__ __align__(16) float As[2][8][68];
    __shared__ __align__(16) float Bs[2][8][132];

    const int z = blockIdx.z;
    const float* W    = (z == 0) ? W0  : (z == 1) ? W1  : W2;
    const float* bias = (z == 0) ? b0_ : (z == 1) ? b1_ : b2_;
    float*       C    = (z == 0) ? C0  : (z == 1) ? C1  : C2;

    const int tid  = threadIdx.x;
    const int m0   = blockIdx.y * 64;
    const int n0   = blockIdx.x * 128;
    const int trow = (tid >> 4) << 3;
    const int c0   = (tid & 15) << 2;
    const int r    = tid >> 1;
    const int q    = (tid & 1) << 2;

    const float* Ap  = A + (size_t)(m0 + r) * 256 + q;
    const float* Wp0 = W + (size_t)(n0 + r) * 256 + q;
    const float* Wp1 = W + (size_t)(n0 + r + 64) * 256 + q;

    unsigned long long acc[8][4];
#pragma unroll
    for (int i = 0; i < 8; ++i)
#pragma unroll
        for (int p = 0; p < 4; ++p) acc[i][p] = 0ULL;

    {
        float4 av  = *(const float4*)Ap;
        float4 wv0 = *(const float4*)Wp0;
        float4 wv1 = *(const float4*)Wp1;
        As[0][q + 0][r] = av.x;  As[0][q + 1][r] = av.y;
        As[0][q + 2][r] = av.z;  As[0][q + 3][r] = av.w;
        Bs[0][q + 0][r] = wv0.x; Bs[0][q + 1][r] = wv0.y;
        Bs[0][q + 2][r] = wv0.z; Bs[0][q + 3][r] = wv0.w;
        Bs[0][q + 0][r + 64] = wv1.x; Bs[0][q + 1][r + 64] = wv1.y;
        Bs[0][q + 2][r + 64] = wv1.z; Bs[0][q + 3][r + 64] = wv1.w;
    }
    __syncthreads();

#pragma unroll 2
    for (int it = 0; it < 32; ++it) {
        const int cur = it & 1;
        float4 avn, wvn0, wvn1;
        if (it < 31) {
            avn  = *(const float4*)(Ap  + (it + 1) * 8);
            wvn0 = *(const float4*)(Wp0 + (it + 1) * 8);
            wvn1 = *(const float4*)(Wp1 + (it + 1) * 8);
        }
#pragma unroll
        for (int kk = 0; kk < 8; ++kk) {
            MMA_KK(As[cur][kk], Bs[cur][kk]);
        }
        if (it < 31) {
            const int nxt = cur ^ 1;
            As[nxt][q + 0][r] = avn.x;  As[nxt][q + 1][r] = avn.y;
            As[nxt][q + 2][r] = avn.z;  As[nxt][q + 3][r] = avn.w;
            Bs[nxt][q + 0][r] = wvn0.x; Bs[nxt][q + 1][r] = wvn0.y;
            Bs[nxt][q + 2][r] = wvn0.z; Bs[nxt][q + 3][r] = wvn0.w;
            Bs[nxt][q + 0][r + 64] = wvn1.x; Bs[nxt][q + 1][r + 64] = wvn1.y;
            Bs[nxt][q + 2][r + 64] = wvn1.z; Bs[nxt][q + 3][r + 64] = wvn1.w;
            __syncthreads();
        }
    }

    float4 bb0 = *(const float4*)&bias[n0 + c0];
    float4 bb1 = *(const float4*)&bias[n0 + c0 + 64];
#pragma unroll
    for (int i = 0; i < 8; ++i) {
        int m = m0 + trow + i;
        float2 v0 = unpack2(acc[i][0]), v1 = unpack2(acc[i][1]);
        float2 v2 = unpack2(acc[i][2]), v3 = unpack2(acc[i][3]);
        float4 o0 = make_float4(v0.x + bb0.x, v0.y + bb0.y, v1.x + bb0.z, v1.y + bb0.w);
        float4 o1 = make_float4(v2.x + bb1.x, v2.y + bb1.y, v3.x + bb1.z, v3.y + bb1.w);
        *(float4*)&C[(size_t)m * 256 + n0 + c0]      = o0;
        *(float4*)&C[(size_t)m * 256 + n0 + c0 + 64] = o1;
    }
}

// ============================================================================
// Scores (R11): 64x128 tile, 128 thr, 8x8/thread, BK=8 double-buffered.
// ============================================================================
__global__ void __launch_bounds__(128, 4) scores_kernel(const float* __restrict__ td)
{
    __shared__ __align__(16) float As[2][8][68];
    __shared__ __align__(16) float Bs[2][8][132];

    const int tid  = threadIdx.x;
    const int bh   = blockIdx.z;
    const int b    = bh >> 2;
    const int h    = bh & 3;
    const int i0   = blockIdx.y * 64;
    const int j0   = blockIdx.x * 128;
    const int trow = (tid >> 4) << 3;
    const int c0   = (tid & 15) << 2;
    const int r    = tid >> 1;
    const int q    = (tid & 1) << 2;

    const float* Qp  = g_Q + ((size_t)(b * Nn) + i0 + r) * 256 + h * 64 + q;
    const float* Kp0 = g_K + ((size_t)(b * Nn) + j0 + r) * 256 + h * 64 + q;
    const float* Kp1 = g_K + ((size_t)(b * Nn) + j0 + r + 64) * 256 + h * 64 + q;

    unsigned long long acc[8][4];
#pragma unroll
    for (int i = 0; i < 8; ++i)
#pragma unroll
        for (int p = 0; p < 4; ++p) acc[i][p] = 0ULL;

    {
        float4 av  = *(const float4*)Qp;
        float4 bv0 = *(const float4*)Kp0;
        float4 bv1 = *(const float4*)Kp1;
        As[0][q + 0][r] = av.x;  As[0][q + 1][r] = av.y;
        As[0][q + 2][r] = av.z;  As[0][q + 3][r] = av.w;
        Bs[0][q + 0][r] = bv0.x; Bs[0][q + 1][r] = bv0.y;
        Bs[0][q + 2][r] = bv0.z; Bs[0][q + 3][r] = bv0.w;
        Bs[0][q + 0][r + 64] = bv1.x; Bs[0][q + 1][r + 64] = bv1.y;
        Bs[0][q + 2][r + 64] = bv1.z; Bs[0][q + 3][r + 64] = bv1.w;
    }
    __syncthreads();

#pragma unroll 2
    for (int it = 0; it < 8; ++it) {
        const int cur = it & 1;
        float4 avn, bvn0, bvn1;
        if (it < 7) {
            avn  = *(const float4*)(Qp  + (it + 1) * 8);
            bvn0 = *(const float4*)(Kp0 + (it + 1) * 8);
            bvn1 = *(const float4*)(Kp1 + (it + 1) * 8);
        }
#pragma unroll
        for (int kk = 0; kk < 8; ++kk) {
            MMA_KK(As[cur][kk], Bs[cur][kk]);
        }
        if (it < 7) {
            const int nxt = cur ^ 1;
            As[nxt][q + 0][r] = avn.x;  As[nxt][q + 1][r] = avn.y;
            As[nxt][q + 2][r] = avn.z;  As[nxt][q + 3][r] = avn.w;
            Bs[nxt][q + 0][r] = bvn0.x; Bs[nxt][q + 1][r] = bvn0.y;
            Bs[nxt][q + 2][r] = bvn0.z; Bs[nxt][q + 3][r] = bvn0.w;
            Bs[nxt][q + 0][r + 64] = bvn1.x; Bs[nxt][q + 1][r + 64] = bvn1.y;
            Bs[nxt][q + 2][r + 64] = bvn1.z; Bs[nxt][q + 3][r + 64] = bvn1.w;
            __syncthreads();
        }
    }

#pragma unroll
    for (int i = 0; i < 8; ++i) {
        int gi = i0 + trow + i;
        const float4* tdr = (const float4*)(td + ((size_t)b * Nn + gi) * Nn + j0);
        float4* Sr = (float4*)(g_S + ((size_t)bh * Nn + gi) * Nn + j0);
        float4 t0 = __ldcs(&tdr[c0 >> 2]);
        float4 t1 = __ldcs(&tdr[(c0 + 64) >> 2]);
        float2 v0 = unpack2(acc[i][0]), v1 = unpack2(acc[i][1]);
        float2 v2 = unpack2(acc[i][2]), v3 = unpack2(acc[i][3]);
        float4 o0 = make_float4(v0.x * 0.125f - 0.1f * t0.x,
                                v0.y * 0.125f - 0.1f * t0.y,
                                v1.x * 0.125f - 0.1f * t0.z,
                                v1.y * 0.125f - 0.1f * t0.w);
        float4 o1 = make_float4(v2.x * 0.125f - 0.1f * t1.x,
                                v2.y * 0.125f - 0.1f * t1.y,
                                v3.x * 0.125f - 0.1f * t1.z,
                                v3.y * 0.125f - 0.1f * t1.w);
        __stcs(&Sr[c0 >> 2], o0);
        __stcs(&Sr[(c0 + 64) >> 2], o1);
    }
}

// ============================================================================
// Fused, 1 row per CTA, 128 threads (4 warps <-> 4 heads), 8 CTAs/SM.
// Smaller CTAs -> more independent memory-phase overlap.
// ============================================================================
constexpr int SURV_CAP = 128;
constexpr int LIST_CAP = 144;

__global__ void __launch_bounds__(128, 8) fused_attn_kernel(
    const int* __restrict__ topk_ptr, float* __restrict__ out_adj)
{
    __shared__ __align__(16) float sc[4][1024];      // 16 KB
    __shared__ __align__(16) float adjs[1024];       //  4 KB
    __shared__ unsigned s_surv[4][SURV_CAP];         //  2 KB
    __shared__ int   jl[4][LIST_CAP];                //  2.25 KB
    __shared__ float av[4][LIST_CAP];                //  2.25 KB
    __shared__ float s_kth[4];
    __shared__ float s_max[4];

    const int tid  = threadIdx.x;
    const int bi   = blockIdx.x;
    const int b    = bi >> 10;
    const int i    = bi & 1023;
    const int warp = tid >> 5, lane = tid & 31;

    // load scores: 4 heads x 1024 floats = 1024 float4; 128 thr x 8
#pragma unroll
    for (int h = 0; h < 4; ++h) {
        const float4* src = (const float4*)(g_S +
            (((size_t)(b * 4 + h) * Nn + i) * Nn));
        ((float4*)sc[h])[tid]       = __ldcs(&src[tid]);
        ((float4*)sc[h])[tid + 128] = __ldcs(&src[tid + 128]);
    }
    ((float4*)adjs)[tid]       = make_float4(0.f, 0.f, 0.f, 0.f);
    ((float4*)adjs)[tid + 128] = make_float4(0.f, 0.f, 0.f, 0.f);
    __syncthreads();

    int kv = *topk_ptr;
    if (kv > Nn) kv = Nn;
    if (kv < 1)  kv = 1;

    // ---- selection: warp h owns head h ----
    {
        const float* row = sc[warp];

        unsigned lmax = 0u;
#pragma unroll
        for (int e = 0; e < 32; ++e)
            lmax = umax(lmax, mapf(row[e * 32 + lane]));
        const unsigned T0 = __reduce_min_sync(0xffffffffu, lmax);
        const unsigned Mx = __reduce_max_sync(0xffffffffu, lmax);

        unsigned* su = s_surv[warp];
        int base = 0;
#pragma unroll
        for (int e = 0; e < 32; ++e) {
            unsigned u = mapf(row[e * 32 + lane]);
            bool p = (u >= T0);
            unsigned m = __ballot_sync(0xffffffffu, p);
            if (p) {
                int pos = base + __popc(m & ((1u << lane) - 1u));
                if (pos < SURV_CAP) su[pos] = u;
            }
            base += __popc(m);
        }
        const int cnt = base;
        __syncwarp();

        unsigned kthU = 0;
        if (kv <= 32 && cnt <= 128) {
            unsigned v0 = (lane      < cnt) ? su[lane]      : 0u;
            unsigned v1 = (lane + 32 < cnt) ? su[lane + 32] : 0u;
            unsigned v2 = (lane + 64 < cnt) ? su[lane + 64] : 0u;
            unsigned v3 = (lane + 96 < cnt) ? su[lane + 96] : 0u;
            unsigned pref = 0; bool got = false;
            for (int bit = 31; bit >= 0; --bit) {
                unsigned cand = pref | (1u << bit);
                unsigned c = (v0 >= cand) + (v1 >= cand) + (v2 >= cand) + (v3 >= cand);
                c = __reduce_add_sync(0xffffffffu, c);
                if (c == (unsigned)kv) {
                    unsigned mn = 0xFFFFFFFFu;
                    if (v0 >= cand) mn = umin(mn, v0);
                    if (v1 >= cand) mn = umin(mn, v1);
                    if (v2 >= cand) mn = umin(mn, v2);
                    if (v3 >= cand) mn = umin(mn, v3);
                    kthU = __reduce_min_sync(0xffffffffu, mn);
                    got = true; break;
                }
                if (c > (unsigned)kv) pref = cand;
            }
            if (!got) kthU = pref;
        } else {
            unsigned pref = 0; bool got = false;
            for (int bit = 31; bit >= 0; --bit) {
                unsigned cand = pref | (1u << bit);
                unsigned c = 0;
#pragma unroll
                for (int e = 0; e < 32; ++e)
                    c += (mapf(row[e * 32 + lane]) >= cand) ? 1u : 0u;
                c = __reduce_add_sync(0xffffffffu, c);
                if (c == (unsigned)kv) {
                    unsigned mn = 0xFFFFFFFFu;
#pragma unroll
                    for (int e = 0; e < 32; ++e) {
                        unsigned u = mapf(row[e * 32 + lane]);
                        if (u >= cand) mn = umin(mn, u);
                    }
                    kthU = __reduce_min_sync(0xffffffffu, mn);
                    got = true; break;
                }
                if (c > (unsigned)kv) pref = cand;
            }
            if (!got) kthU = pref;
        }
        if (lane == 0) { s_kth[warp] = invmap(kthU); s_max[warp] = invmap(Mx); }
    }
    __syncwarp();

    // ---- group phase: warp handles head `warp` ----
    const float kth = s_kth[warp];
    const float mx  = s_max[warp];
    int*   jlh = jl[warp];
    float* avh = av[warp];
    const float* rowsc = sc[warp];

    int base2 = 0;
#pragma unroll
    for (int r = 0; r < 32; ++r) {
        int j = r * 32 + lane;
        float s = rowsc[j];
        bool p = (s >= kth);
        unsigned m = __ballot_sync(0xffffffffu, p);
        if (p) {
            int pos = base2 + __popc(m & ((1u << lane) - 1u));
            if (pos < LIST_CAP) { jlh[pos] = j; avh[pos] = s; }
        }
        base2 += __popc(m);
    }
    __syncwarp();
    int cnt2 = (base2 > LIST_CAP) ? LIST_CAP : base2;

    float lsum = 0.f;
    for (int l = lane; l < cnt2; l += 32) {
        float e = __expf(avh[l] - mx);
        avh[l] = e;
        lsum += e;
    }
#pragma unroll
    for (int o = 16; o; o >>= 1) lsum += __shfl_xor_sync(0xffffffffu, lsum, o);
    const float inv = 1.f / lsum;  // max survives -> lsum >= 1

    for (int l = lane; l < cnt2; l += 32) {
        float a = avh[l] * inv;
        avh[l] = a;
        atomicAdd(&adjs[jlh[l]], 0.25f * a);
    }
    __syncwarp();

    // sparse attn @ V: float2 gather, 8-wide unroll (8 LDG.64 in flight)
    {
        const float2* vb2 = (const float2*)(g_V + (size_t)b * Nn * 256 + warp * 64);
        float ax = 0.f, ay = 0.f;
        int l = 0;
        for (; l + 8 <= cnt2; l += 8) {
            float2 x0 = vb2[(size_t)jlh[l]     * 128 + lane];
            float2 x1 = vb2[(size_t)jlh[l + 1] * 128 + lane];
            float2 x2 = vb2[(size_t)jlh[l + 2] * 128 + lane];
            float2 x3 = vb2[(size_t)jlh[l + 3] * 128 + lane];
            float2 x4 = vb2[(size_t)jlh[l + 4] * 128 + lane];
            float2 x5 = vb2[(size_t)jlh[l + 5] * 128 + lane];
            float2 x6 = vb2[(size_t)jlh[l + 6] * 128 + lane];
            float2 x7 = vb2[(size_t)jlh[l + 7] * 128 + lane];
            float a0 = avh[l],     a1 = avh[l + 1], a2 = avh[l + 2], a3 = avh[l + 3];
            float a4 = avh[l + 4], a5 = avh[l + 5], a6 = avh[l + 6], a7 = avh[l + 7];
            ax = fmaf(a0, x0.x, ax); ay = fmaf(a0, x0.y, ay);
            ax = fmaf(a1, x1.x, ax); ay = fmaf(a1, x1.y, ay);
            ax = fmaf(a2, x2.x, ax); ay = fmaf(a2, x2.y, ay);
            ax = fmaf(a3, x3.x, ax); ay = fmaf(a3, x3.y, ay);
            ax = fmaf(a4, x4.x, ax); ay = fmaf(a4, x4.y, ay);
            ax = fmaf(a5, x5.x, ax); ay = fmaf(a5, x5.y, ay);
            ax = fmaf(a6, x6.x, ax); ay = fmaf(a6, x6.y, ay);
            ax = fmaf(a7, x7.x, ax); ay = fmaf(a7, x7.y, ay);
        }
        for (; l < cnt2; ++l) {
            float2 x = vb2[(size_t)jlh[l] * 128 + lane];
            float a = avh[l];
            ax = fmaf(a, x.x, ax); ay = fmaf(a, x.y, ay);
        }
        float2* mrow2 = (float2*)(g_M + ((size_t)(b * Nn) + i) * 256 + warp * 64);
        mrow2[lane] = make_float2(ax, ay);
    }
    __syncthreads();

    {
        float4* arow = (float4*)(out_adj + ((size_t)(b * Nn) + i) * Nn);
        __stcs(&arow[tid],       ((const float4*)adjs)[tid]);
        __stcs(&arow[tid + 128], ((const float4*)adjs)[tid + 128]);
    }
}

// ============================================================================
extern "C" void kernel_launch(void* const* d_in, const int* in_sizes, int n_in,
                              void* d_out, int out_size)
{
    const float* h_in = (const float*)d_in[0];
    const float* td   = (const float*)d_in[1];
    const float* Wq   = (const float*)d_in[2];
    const float* bq   = (const float*)d_in[3];
    const float* Wk   = (const float*)d_in[4];
    const float* bk   = (const float*)d_in[5];
    const float* Wv   = (const float*)d_in[6];
    const float* bv   = (const float*)d_in[7];
    const float* Wo   = (const float*)d_in[8];
    const float* bo   = (const float*)d_in[9];
    const int*   tk   = (const int*)d_in[10];

    float* out_adj = (float*)d_out;
    float* out_msg = out_adj + (size_t)Bn * Nn * Nn;

    float *q, *k, *v, *m;
    cudaGetSymbolAddress((void**)&q, g_Q);
    cudaGetSymbolAddress((void**)&k, g_K);
    cudaGetSymbolAddress((void**)&v, g_V);
    cudaGetSymbolAddress((void**)&m, g_M);

    gemm_qkv_kernel<<<dim3(2, 128, 3), 128>>>(h_in, Wq, Wk, Wv, bq, bk, bv, q, k, v);
    scores_kernel<<<dim3(Nn / 128, Nn / 64, Bn * Hn), 128>>>(td);
    fused_attn_kernel<<<ROWS, 128>>>(tk, out_adj);
    gemm_qkv_kernel<<<dim3(2, 128, 1), 128>>>(m, Wo, Wo, Wo, bo, bo, bo,
                                              out_msg, out_msg, out_msg);
}